// round 5
// baseline (speedup 1.0000x reference)
#include <cuda_runtime.h>
#include <cstdint>
#include <cstddef>

#define NROWS (256*1024)
#define CDIM 1024
#define BDIM 256

typedef unsigned long long u64;

// ---------------- device scratch (static globals, no allocation) -----------
__device__ __align__(16) float g_m[(size_t)NROWS * 64];   // m_next, (c,b,64)
__device__ float g_adj[2 * CDIM];                          // clipped adj (k,c)
__device__ float g_sbias[CDIM * 64];                       // bs1 + kc@Ws1[64:]
__device__ float g_nbias[CDIM * 2 * 64];                   // bn1 + clip(kc)@Wn1[192:]
__device__ int   g_list[NROWS];
__device__ int   g_cnt;

// ---------------- helpers --------------------------------------------------
__device__ __forceinline__ u64 pack2(float a, float b) {
    u64 r;
    asm("mov.b64 %0,{%1,%2};" : "=l"(r)
        : "r"(__float_as_uint(a)), "r"(__float_as_uint(b)));
    return r;
}
__device__ __forceinline__ void unpack2(u64 v, float& a, float& b) {
    unsigned lo, hi;
    asm("mov.b64 {%0,%1},%2;" : "=r"(lo), "=r"(hi) : "l"(v));
    a = __uint_as_float(lo); b = __uint_as_float(hi);
}
// Blackwell packed fp32 FMA (2 IEEE fp32 FMAs / instruction)
__device__ __forceinline__ void ffma2(u64& acc, u64 a, u64 b) {
    asm("fma.rn.f32x2 %0,%1,%2,%0;" : "+l"(acc) : "l"(a), "l"(b));
}
__device__ __forceinline__ float clip5(float x)  { return fminf(fmaxf(x, -5.f), 5.f); }
__device__ __forceinline__ float clip50(float x) { return fminf(fmaxf(x, -50.f), 50.f); }
__device__ __forceinline__ float sigf(float x)   { return __fdividef(1.f, 1.f + __expf(-x)); }
__device__ __forceinline__ float tanh_(float x)  { return 1.f - __fdividef(2.f, __expf(2.f * x) + 1.f); }

// ---------------- tiny prep kernels ----------------------------------------
__global__ void k_zero() { if (threadIdx.x == 0) g_cnt = 0; }

// adj[k][d] = clip( (sum_c a0[c]*graphs[k][c][d]) / max(sum a0, 1), -5, 5 )
__global__ __launch_bounds__(128) void k_adj(const int* __restrict__ qt,
                                             const float* __restrict__ oneh,
                                             const float* __restrict__ graphs) {
    __shared__ float a0[CDIM];
    __shared__ float sden;
    int t = blockIdx.x * 128 + threadIdx.x;   // 16*128 = 2048 = K*C
    int k = t >> 10, d = t & 1023;
    int q0 = qt[0];
    for (int i = threadIdx.x; i < CDIM; i += 128) a0[i] = oneh[(size_t)q0 * CDIM + i];
    __syncthreads();
    if (threadIdx.x == 0) {
        float s = 0.f;
        for (int i = 0; i < CDIM; i++) s += a0[i];
        sden = fmaxf(s, 1.f);
    }
    __syncthreads();
    const float* gc = graphs + (size_t)k * CDIM * CDIM + d;
    float acc = 0.f;
#pragma unroll 8
    for (int i = 0; i < CDIM; i++) acc += a0[i] * gc[(size_t)i * CDIM];
    g_adj[k * CDIM + d] = clip5(acc / sden);
}

// fold kc-embedding halves of layer-1 inputs into per-c biases
__global__ __launch_bounds__(64) void k_bias(const float* __restrict__ kc,
                                             const float* __restrict__ Ws1,
                                             const float* __restrict__ bs1,
                                             const float* __restrict__ Wn1,
                                             const float* __restrict__ bn1) {
    __shared__ float e[64], ec[64];
    int c = blockIdx.x, j = threadIdx.x;
    float v = kc[c * 64 + j];
    e[j] = v; ec[j] = clip5(v);
    __syncthreads();
    float s = bs1[j];
#pragma unroll 4
    for (int i = 0; i < 64; i++) s += e[i] * Ws1[(64 + i) * 64 + j];
    g_sbias[c * 64 + j] = s;
#pragma unroll
    for (int k = 0; k < 2; k++) {
        float a = bn1[k * 64 + j];
#pragma unroll 4
        for (int i = 0; i < 64; i++) a += ec[i] * Wn1[k * 16384 + (192 + i) * 64 + j];
        g_nbias[(c * 2 + k) * 64 + j] = a;
    }
}

// collect mask==1 rows (row id = c*256 + b)
__global__ __launch_bounds__(1024) void k_list(const int* __restrict__ qt,
                                               const float* __restrict__ oneh) {
    int b = blockIdx.x, cc = threadIdx.x;
    float m = oneh[(size_t)qt[b] * CDIM + cc];
    if (m > 0.5f) {
        int p = atomicAdd(&g_cnt, 1);
        g_list[p] = cc * 256 + b;
    }
}

// ---------------- K1: neighbor path for ALL rows → g_m ---------------------
// dyn smem floats: W1s[0,8192) W2s[8192,16384) X[16384,33024)
//                  Hs[33024,49664) NB[49664,49792) B2[49792,49920)
__global__ __launch_bounds__(256) void k_neigh(const float* __restrict__ ht,
                                               const float* __restrict__ Wn1,
                                               const float* __restrict__ Wn2,
                                               const float* __restrict__ bn2,
                                               const float* __restrict__ nw) {
    extern __shared__ float sm[];
    float* W1s = sm;
    float* W2s = sm + 8192;
    float* X   = sm + 16384;
    float* Hs  = sm + 33024;
    float* NB  = sm + 49664;
    float* B2  = sm + 49792;

    const int tid = threadIdx.x;   // = b
    const int c   = blockIdx.x;

    for (int idx = tid; idx < 8192; idx += 256) {
        int k = idx >> 12, r = idx & 4095;
        W1s[idx] = Wn1[k * 16384 + 8192 + r];   // rows 128..191 (ht part)
        W2s[idx] = Wn2[idx];
    }
    if (tid < 128) {
        NB[tid] = g_nbias[c * 128 + tid];
        B2[tid] = bn2[tid];
    }
    {
        const float4* hr = (const float4*)(ht + ((size_t)tid * CDIM + c) * 64);
        float* xb = X + tid * 65;
#pragma unroll
        for (int q = 0; q < 16; q++) {
            float4 v = hr[q];
            xb[4*q+0] = clip5(v.x); xb[4*q+1] = clip5(v.y);
            xb[4*q+2] = clip5(v.z); xb[4*q+3] = clip5(v.w);
        }
    }
    __syncthreads();

    const float adj0 = g_adj[c];
    const float adj1 = g_adj[CDIM + c];
    const float wmix = fminf(fmaxf(nw[0], 0.1f), 0.9f);

    float nf[64];
#pragma unroll
    for (int k = 0; k < 2; k++) {
        u64 acc[32];
#pragma unroll
        for (int p = 0; p < 32; p++) acc[p] = pack2(NB[k*64 + 2*p], NB[k*64 + 2*p + 1]);
        const float* xb = X + tid * 65;
#pragma unroll 2
        for (int i = 0; i < 64; i++) {
            float xi = xb[i];
            u64 xp = pack2(xi, xi);
            const ulonglong2* wr = (const ulonglong2*)(W1s + k * 4096 + i * 64);
#pragma unroll
            for (int p = 0; p < 16; p++) {
                ulonglong2 w = wr[p];
                ffma2(acc[2*p],   xp, w.x);
                ffma2(acc[2*p+1], xp, w.y);
            }
        }
        float* hb = Hs + tid * 65;
#pragma unroll
        for (int p = 0; p < 32; p++) {
            float a, b; unpack2(acc[p], a, b);
            hb[2*p] = fmaxf(a, 0.f); hb[2*p+1] = fmaxf(b, 0.f);
        }
#pragma unroll
        for (int p = 0; p < 32; p++) acc[p] = pack2(B2[k*64 + 2*p], B2[k*64 + 2*p + 1]);
#pragma unroll 2
        for (int i = 0; i < 64; i++) {
            float hi = hb[i];
            u64 hp = pack2(hi, hi);
            const ulonglong2* wr = (const ulonglong2*)(W2s + k * 4096 + i * 64);
#pragma unroll
            for (int p = 0; p < 16; p++) {
                ulonglong2 w = wr[p];
                ffma2(acc[2*p],   hp, w.x);
                ffma2(acc[2*p+1], hp, w.y);
            }
        }
#pragma unroll
        for (int p = 0; p < 32; p++) {
            float a, b; unpack2(acc[p], a, b);
            a = fminf(fmaxf(a, 0.f), 5.f);   // relu then clip(-5,5)
            b = fminf(fmaxf(b, 0.f), 5.f);
            if (k == 0) {
                nf[2*p]   = clip5(adj0 * a);
                nf[2*p+1] = clip5(adj0 * b);
            } else {
                nf[2*p]   = clip5(wmix * nf[2*p]   + (1.f - wmix) * adj1 * a);
                nf[2*p+1] = clip5(wmix * nf[2*p+1] + (1.f - wmix) * adj1 * b);
            }
        }
    }
    float4* out = (float4*)(g_m + ((size_t)c * 256 + tid) * 64);
#pragma unroll
    for (int q = 0; q < 16; q++)
        out[q] = make_float4(clip50(nf[4*q+0]), clip50(nf[4*q+1]),
                             clip50(nf[4*q+2]), clip50(nf[4*q+3]));
}

// ---------------- K2: self-MLP fixup at mask==1 rows -----------------------
__global__ __launch_bounds__(64) void k_self(const float* __restrict__ ht,
                                             const float* __restrict__ Ws1,
                                             const float* __restrict__ Ws2,
                                             const float* __restrict__ bs2) {
    __shared__ float xs[64], us[64];
    const int cnt = g_cnt;
    const int j = threadIdx.x;
    for (int it = blockIdx.x; it < cnt; it += gridDim.x) {
        int row = g_list[it];
        int c = row >> 8, b = row & 255;
        xs[j] = ht[((size_t)b * CDIM + c) * 64 + j];
        __syncthreads();
        float a = g_sbias[c * 64 + j];
#pragma unroll 4
        for (int i = 0; i < 64; i++) a += xs[i] * Ws1[i * 64 + j];
        us[j] = fmaxf(a, 0.f);
        __syncthreads();
        float o = bs2[j];
#pragma unroll 4
        for (int i = 0; i < 64; i++) o += us[i] * Ws2[i * 64 + j];
        o = fminf(fmaxf(o, 0.f), 10.f);   // relu then clip(-10,10)
        g_m[(size_t)row * 64 + j] = clip50(o);
        __syncthreads();
    }
}

// ---------------- K3: gated residual + GRU + output dot (fused) ------------
// dyn smem floats: WS[0,24576) BufA[24576,37056) BufB[37056,49536) WPs[49536,49600)
__global__ __launch_bounds__(192) void k_gru(const float* __restrict__ ht,
                                             const float* __restrict__ We,  const float* __restrict__ be,
                                             const float* __restrict__ Wa,  const float* __restrict__ ba,
                                             const float* __restrict__ Wih, const float* __restrict__ bih,
                                             const float* __restrict__ Whh, const float* __restrict__ bhh,
                                             const float* __restrict__ Wp,  const float* __restrict__ bp,
                                             const float* __restrict__ eaw, float* __restrict__ y) {
    extern __shared__ float sm[];
    float* WS   = sm;            // reused across stages
    float* BufA = sm + 24576;    // m, then res (stride 65)
    float* BufB = sm + 37056;    // ht (stride 65)
    float* WPs  = sm + 49536;

    const int tid  = threadIdx.x;
    const int row  = blockIdx.x * 192 + tid;
    const bool live = row < NROWS;
    const int lrow = live ? row : 0;
    const int c = lrow >> 8, b = lrow & 255;

    // stage-1 weights: We -> WS[0:4096], Wa -> WS[4096:8192]
    for (int idx = tid; idx < 1024; idx += 192) ((float4*)WS)[idx]          = ((const float4*)We)[idx];
    for (int idx = tid; idx < 1024; idx += 192) ((float4*)(WS + 4096))[idx] = ((const float4*)Wa)[idx];
    if (tid < 64) WPs[tid] = Wp[tid];
    {
        const float4* mr = (const float4*)(g_m + (size_t)lrow * 64);
        const float4* hr = (const float4*)(ht + ((size_t)b * CDIM + c) * 64);
        float* ab = BufA + tid * 65;
        float* bb = BufB + tid * 65;
#pragma unroll
        for (int q = 0; q < 16; q++) {
            float4 v = mr[q];
            ab[4*q+0] = v.x; ab[4*q+1] = v.y; ab[4*q+2] = v.z; ab[4*q+3] = v.w;
            float4 u = hr[q];
            bb[4*q+0] = u.x; bb[4*q+1] = u.y; bb[4*q+2] = u.z; bb[4*q+3] = u.w;
        }
    }
    __syncthreads();

    // res = m - g*sig(m@We+be)*m + g*tanh(m@Wa+ba)   (in place over BufA)
    {
        u64 aS[32], aT[32];
#pragma unroll
        for (int p = 0; p < 32; p++) {
            aS[p] = pack2(__ldg(be + 2*p), __ldg(be + 2*p + 1));
            aT[p] = pack2(__ldg(ba + 2*p), __ldg(ba + 2*p + 1));
        }
        const float* mb = BufA + tid * 65;
#pragma unroll 2
        for (int i = 0; i < 64; i++) {
            float mi = mb[i];
            u64 mp = pack2(mi, mi);
            const ulonglong2* wS = (const ulonglong2*)(WS + i * 64);
            const ulonglong2* wT = (const ulonglong2*)(WS + 4096 + i * 64);
#pragma unroll
            for (int p = 0; p < 16; p++) {
                ulonglong2 w = wS[p];
                ffma2(aS[2*p], mp, w.x); ffma2(aS[2*p+1], mp, w.y);
                w = wT[p];
                ffma2(aT[2*p], mp, w.x); ffma2(aT[2*p+1], mp, w.y);
            }
        }
        const float g = __ldg(eaw + c);
        float* ab = BufA + tid * 65;
#pragma unroll
        for (int p = 0; p < 32; p++) {
            float s0, s1, t0, t1;
            unpack2(aS[p], s0, s1);
            unpack2(aT[p], t0, t1);
            float m0 = ab[2*p], m1 = ab[2*p+1];
            ab[2*p]   = m0 - g * sigf(s0) * m0 + g * tanh_(t0);
            ab[2*p+1] = m1 - g * sigf(s1) * m1 + g * tanh_(t1);
        }
    }
    __syncthreads();   // done reading We/Wa before WS overwrite

    // stage-2 weights: Wih -> WS[0:12288], Whh -> WS[12288:24576]
    for (int idx = tid; idx < 3072; idx += 192) ((float4*)WS)[idx]           = ((const float4*)Wih)[idx];
    for (int idx = tid; idx < 3072; idx += 192) ((float4*)(WS + 12288))[idx] = ((const float4*)Whh)[idx];
    __syncthreads();

    // GRU in 16-feature chunks; accumulate output dot on the fly
    float yacc = __ldg(bp);
    const float* rb = BufA + tid * 65;   // res
    const float* hb = BufB + tid * 65;   // ht
#pragma unroll 1
    for (int jc = 0; jc < 4; jc++) {
        const int j0 = jc * 16;
        u64 A[6][8];   // ir iz in hr hz hn, 8 feature-pairs each
#pragma unroll
        for (int p = 0; p < 8; p++) {
            int j = j0 + 2*p;
            A[0][p] = pack2(__ldg(bih + j),       __ldg(bih + j + 1));
            A[1][p] = pack2(__ldg(bih + 64 + j),  __ldg(bih + 64 + j + 1));
            A[2][p] = pack2(__ldg(bih + 128 + j), __ldg(bih + 128 + j + 1));
            A[3][p] = pack2(__ldg(bhh + j),       __ldg(bhh + j + 1));
            A[4][p] = pack2(__ldg(bhh + 64 + j),  __ldg(bhh + 64 + j + 1));
            A[5][p] = pack2(__ldg(bhh + 128 + j), __ldg(bhh + 128 + j + 1));
        }
#pragma unroll 2
        for (int i = 0; i < 64; i++) {
            float ri = rb[i], hi = hb[i];
            u64 rp = pack2(ri, ri), hp = pack2(hi, hi);
            const ulonglong2* wi = (const ulonglong2*)(WS + i * 192 + j0);
            const ulonglong2* wh = (const ulonglong2*)(WS + 12288 + i * 192 + j0);
#pragma unroll
            for (int q = 0; q < 4; q++) {
                ulonglong2 w;
                w = wi[q];      ffma2(A[0][2*q], rp, w.x); ffma2(A[0][2*q+1], rp, w.y);
                w = wi[q+16];   ffma2(A[1][2*q], rp, w.x); ffma2(A[1][2*q+1], rp, w.y);
                w = wi[q+32];   ffma2(A[2][2*q], rp, w.x); ffma2(A[2][2*q+1], rp, w.y);
                w = wh[q];      ffma2(A[3][2*q], hp, w.x); ffma2(A[3][2*q+1], hp, w.y);
                w = wh[q+16];   ffma2(A[4][2*q], hp, w.x); ffma2(A[4][2*q+1], hp, w.y);
                w = wh[q+32];   ffma2(A[5][2*q], hp, w.x); ffma2(A[5][2*q+1], hp, w.y);
            }
        }
#pragma unroll
        for (int p = 0; p < 8; p++) {
            int j = j0 + 2*p;
            float ir0, ir1, iz0, iz1, in0, in1, hr0, hr1, hz0, hz1, hn0, hn1;
            unpack2(A[0][p], ir0, ir1);
            unpack2(A[1][p], iz0, iz1);
            unpack2(A[2][p], in0, in1);
            unpack2(A[3][p], hr0, hr1);
            unpack2(A[4][p], hz0, hz1);
            unpack2(A[5][p], hn0, hn1);
            float h0 = hb[j], h1 = hb[j+1];
            float r0 = sigf(ir0 + hr0), z0 = sigf(iz0 + hz0);
            float n0 = tanh_(in0 + r0 * hn0);
            float hx0 = (1.f - z0) * n0 + z0 * h0;
            float r1 = sigf(ir1 + hr1), z1 = sigf(iz1 + hz1);
            float n1 = tanh_(in1 + r1 * hn1);
            float hx1 = (1.f - z1) * n1 + z1 * h1;
            yacc += hx0 * WPs[j] + hx1 * WPs[j+1];
        }
    }
    if (live) y[(size_t)b * CDIM + c] = sigf(yacc);
}

// ---------------- launch ----------------------------------------------------
static const int SMEM_NEIGH = 49920 * 4;   // 199,680 B
static const int SMEM_GRU   = 49600 * 4;   // 198,400 B

extern "C" void kernel_launch(void* const* d_in, const int* in_sizes, int n_in,
                              void* d_out, int out_size) {
    // one-time opt-in to >48KB dyn smem (runs on first correctness call,
    // outside graph capture; attribute is persistent)
    static bool once = []() {
        cudaFuncSetAttribute(k_neigh, cudaFuncAttributeMaxDynamicSharedMemorySize, SMEM_NEIGH);
        cudaFuncSetAttribute(k_gru,   cudaFuncAttributeMaxDynamicSharedMemorySize, SMEM_GRU);
        return true;
    }();
    (void)once; (void)in_sizes; (void)n_in;

    const int*   qt    = (const int*)  d_in[1];
    const float* ht    = (const float*)d_in[2];
    const float* oneh  = (const float*)d_in[3];
    const float* kc    = (const float*)d_in[4];
    const float* grph  = (const float*)d_in[5];
    const float* nw    = (const float*)d_in[6];
    const float* Ws1   = (const float*)d_in[7];
    const float* bs1   = (const float*)d_in[8];
    const float* Ws2   = (const float*)d_in[9];
    const float* bs2   = (const float*)d_in[10];
    const float* Wn1   = (const float*)d_in[11];
    const float* bn1   = (const float*)d_in[12];
    const float* Wn2   = (const float*)d_in[13];
    const float* bn2   = (const float*)d_in[14];
    const float* eaw   = (const float*)d_in[15];
    const float* We    = (const float*)d_in[16];
    const float* be    = (const float*)d_in[17];
    const float* Wa    = (const float*)d_in[18];
    const float* ba    = (const float*)d_in[19];
    const float* Wih   = (const float*)d_in[20];
    const float* bih   = (const float*)d_in[21];
    const float* Whh   = (const float*)d_in[22];
    const float* bhh   = (const float*)d_in[23];
    const float* Wp    = (const float*)d_in[24];
    const float* bp    = (const float*)d_in[25];
    float* y = (float*)d_out;

    k_zero<<<1, 1>>>();
    k_adj<<<16, 128>>>(qt, oneh, grph);
    k_bias<<<CDIM, 64>>>(kc, Ws1, bs1, Wn1, bn1);
    k_list<<<BDIM, 1024>>>(qt, oneh);
    k_neigh<<<CDIM, 256, SMEM_NEIGH>>>(ht, Wn1, Wn2, bn2, nw);
    k_self<<<1024, 64>>>(ht, Ws1, Ws2, bs2);
    k_gru<<<(NROWS + 191) / 192, 192, SMEM_GRU>>>(ht, We, be, Wa, ba,
                                                  Wih, bih, Whh, bhh,
                                                  Wp, bp, eaw, y);
}